// round 2
// baseline (speedup 1.0000x reference)
#include <cuda_runtime.h>
#include <math.h>

#define D_MODEL 1024
#define S_LEN   2048
#define BATCH   2
#define HEADS   16
#define DEPTH   64
#define ROWS    (BATCH * S_LEN)     // 4096
#define BH      (BATCH * HEADS)     // 32

#define OUT_ELEMS  ((size_t)ROWS * D_MODEL)              // 4,194,304
#define ATTN_ELEMS ((size_t)BH * S_LEN * S_LEN)          // 134,217,728

// Scratch (device globals — allocation-guard safe)
__device__ float g_q[ROWS * D_MODEL];
__device__ float g_k[ROWS * D_MODEL];
__device__ float g_v[ROWS * D_MODEL];
__device__ float g_ctx[ROWS * D_MODEL];
__device__ float g_attn_scratch[ATTN_ELEMS];  // used only if attn is not part of d_out

// ---------------------------------------------------------------------------
// Generic NN GEMM with bias: C[M,N] = A[M,K] @ B[K,N] + bias
// A row stride = K, B row stride = N, C row stride = N.
// BM=BN=64, BK=16, 256 threads (16x16), 4x4 micro-tile per thread.
// ---------------------------------------------------------------------------
__global__ void gemm_nn_bias(const float* __restrict__ A,
                             const float* __restrict__ B,
                             const float* __restrict__ bias,
                             float* __restrict__ C,
                             int M, int N, int K) {
    __shared__ float As[64][17];   // As[m][k]
    __shared__ float Bs[16][65];   // Bs[k][n]

    const int tx = threadIdx.x, ty = threadIdx.y;
    const int tid = ty * 16 + tx;
    const int m0 = blockIdx.y * 64;
    const int n0 = blockIdx.x * 64;

    float acc[4][4] = {};

    for (int kt = 0; kt < K; kt += 16) {
        // load A tile: 64 rows x 16 k
        #pragma unroll
        for (int l = tid; l < 64 * 16; l += 256) {
            int m = l >> 4, k = l & 15;
            As[m][k] = A[(size_t)(m0 + m) * K + kt + k];
        }
        // load B tile: 16 k x 64 n
        #pragma unroll
        for (int l = tid; l < 16 * 64; l += 256) {
            int k = l >> 6, n = l & 63;
            Bs[k][n] = B[(size_t)(kt + k) * N + n0 + n];
        }
        __syncthreads();

        #pragma unroll
        for (int k = 0; k < 16; k++) {
            float a[4], b[4];
            #pragma unroll
            for (int i = 0; i < 4; i++) a[i] = As[ty * 4 + i][k];
            #pragma unroll
            for (int j = 0; j < 4; j++) b[j] = Bs[k][tx * 4 + j];
            #pragma unroll
            for (int i = 0; i < 4; i++)
                #pragma unroll
                for (int j = 0; j < 4; j++)
                    acc[i][j] += a[i] * b[j];
        }
        __syncthreads();
    }

    #pragma unroll
    for (int i = 0; i < 4; i++) {
        int m = m0 + ty * 4 + i;
        #pragma unroll
        for (int j = 0; j < 4; j++) {
            int n = n0 + tx * 4 + j;
            float r = acc[i][j];
            if (bias) r += bias[n];
            C[(size_t)m * N + n] = r;
        }
    }
}

// ---------------------------------------------------------------------------
// Logits: per (b,h): L[q][s] = scale * sum_d Q[q][d] * K[s][d]
// Q/K packed in [4096, 1024] with head offset; row stride 1024.
// M=N=2048, Kdim=64. grid(32, 32, 32), block(16,16).
// ---------------------------------------------------------------------------
__global__ void logits_kernel(const float* __restrict__ q,
                              const float* __restrict__ kmat,
                              float* __restrict__ attn) {
    const int bh = blockIdx.z;
    const int b = bh / HEADS, h = bh % HEADS;
    const float* Q  = q    + (size_t)b * S_LEN * D_MODEL + h * DEPTH;
    const float* Kp = kmat + (size_t)b * S_LEN * D_MODEL + h * DEPTH;
    float* out = attn + (size_t)bh * S_LEN * S_LEN;

    __shared__ float As[64][17];   // As[m][kk]
    __shared__ float Bs[64][17];   // Bs[n][kk]

    const int tx = threadIdx.x, ty = threadIdx.y;
    const int tid = ty * 16 + tx;
    const int m0 = blockIdx.y * 64;
    const int n0 = blockIdx.x * 64;

    float acc[4][4] = {};

    for (int kt = 0; kt < DEPTH; kt += 16) {
        #pragma unroll
        for (int l = tid; l < 64 * 16; l += 256) {
            int m = l >> 4, kk = l & 15;
            As[m][kk] = Q[(size_t)(m0 + m) * D_MODEL + kt + kk];
        }
        #pragma unroll
        for (int l = tid; l < 64 * 16; l += 256) {
            int n = l >> 4, kk = l & 15;
            Bs[n][kk] = Kp[(size_t)(n0 + n) * D_MODEL + kt + kk];
        }
        __syncthreads();

        #pragma unroll
        for (int kk = 0; kk < 16; kk++) {
            float a[4], b[4];
            #pragma unroll
            for (int i = 0; i < 4; i++) a[i] = As[ty * 4 + i][kk];
            #pragma unroll
            for (int j = 0; j < 4; j++) b[j] = Bs[tx * 4 + j][kk];
            #pragma unroll
            for (int i = 0; i < 4; i++)
                #pragma unroll
                for (int j = 0; j < 4; j++)
                    acc[i][j] += a[i] * b[j];
        }
        __syncthreads();
    }

    const float scale = 0.125f;  // 1/sqrt(64)
    #pragma unroll
    for (int i = 0; i < 4; i++) {
        int m = m0 + ty * 4 + i;
        #pragma unroll
        for (int j = 0; j < 4; j++) {
            int n = n0 + tx * 4 + j;
            out[(size_t)m * S_LEN + n] = acc[i][j] * scale;
        }
    }
}

// ---------------------------------------------------------------------------
// Softmax over last dim of attn rows. One block (256 thr) per row of 2048.
// ---------------------------------------------------------------------------
__global__ void softmax_kernel(float* __restrict__ attn) {
    __shared__ float buf[S_LEN];
    __shared__ float red[8];

    const size_t row = blockIdx.x;
    float* p = attn + row * S_LEN;
    const int tid = threadIdx.x;
    const int lane = tid & 31, warp = tid >> 5;

    // load + local max
    float mx = -INFINITY;
    #pragma unroll
    for (int i = 0; i < 8; i++) {
        float v = p[tid + i * 256];
        buf[tid + i * 256] = v;
        mx = fmaxf(mx, v);
    }
    // warp-reduce max
    #pragma unroll
    for (int o = 16; o > 0; o >>= 1) mx = fmaxf(mx, __shfl_xor_sync(0xffffffffu, mx, o));
    if (lane == 0) red[warp] = mx;
    __syncthreads();
    if (warp == 0) {
        float v = (lane < 8) ? red[lane] : -INFINITY;
        #pragma unroll
        for (int o = 4; o > 0; o >>= 1) v = fmaxf(v, __shfl_xor_sync(0xffffffffu, v, o));
        if (lane == 0) red[0] = v;
    }
    __syncthreads();
    mx = red[0];

    // sum of exp
    float s = 0.f;
    #pragma unroll
    for (int i = 0; i < 8; i++) s += __expf(buf[tid + i * 256] - mx);
    #pragma unroll
    for (int o = 16; o > 0; o >>= 1) s += __shfl_xor_sync(0xffffffffu, s, o);
    if (lane == 0) red[warp] = s;
    __syncthreads();
    if (warp == 0) {
        float v = (lane < 8) ? red[lane] : 0.f;
        #pragma unroll
        for (int o = 4; o > 0; o >>= 1) v += __shfl_xor_sync(0xffffffffu, v, o);
        if (lane == 0) red[0] = v;
    }
    __syncthreads();
    const float inv = 1.f / red[0];

    #pragma unroll
    for (int i = 0; i < 8; i++) {
        int idx = tid + i * 256;
        p[idx] = __expf(buf[idx] - mx) * inv;
    }
}

// ---------------------------------------------------------------------------
// Context: per (b,h): ctx[q][d] = sum_s attn[q][s] * V[s][d]
// M=2048 (q), N=64 (d), K=2048 (s). grid(32 qtiles, 1, 32 bh), block(16,16).
// ---------------------------------------------------------------------------
__global__ void ctx_kernel(const float* __restrict__ attn,
                           const float* __restrict__ v,
                           float* __restrict__ ctx) {
    const int bh = blockIdx.z;
    const int b = bh / HEADS, h = bh % HEADS;
    const float* Ap = attn + (size_t)bh * S_LEN * S_LEN;
    const float* Vp = v    + (size_t)b * S_LEN * D_MODEL + h * DEPTH;
    float* Cp = ctx + (size_t)b * S_LEN * D_MODEL + h * DEPTH;

    __shared__ float As[64][17];   // As[m][ss]
    __shared__ float Bs[16][65];   // Bs[ss][n]

    const int tx = threadIdx.x, ty = threadIdx.y;
    const int tid = ty * 16 + tx;
    const int m0 = blockIdx.x * 64;

    float acc[4][4] = {};

    for (int st = 0; st < S_LEN; st += 16) {
        #pragma unroll
        for (int l = tid; l < 64 * 16; l += 256) {
            int m = l >> 4, ss = l & 15;
            As[m][ss] = Ap[(size_t)(m0 + m) * S_LEN + st + ss];
        }
        #pragma unroll
        for (int l = tid; l < 16 * 64; l += 256) {
            int ss = l >> 6, n = l & 63;
            Bs[ss][n] = Vp[(size_t)(st + ss) * D_MODEL + n];
        }
        __syncthreads();

        #pragma unroll
        for (int ss = 0; ss < 16; ss++) {
            float a[4], b[4];
            #pragma unroll
            for (int i = 0; i < 4; i++) a[i] = As[ty * 4 + i][ss];
            #pragma unroll
            for (int j = 0; j < 4; j++) b[j] = Bs[ss][tx * 4 + j];
            #pragma unroll
            for (int i = 0; i < 4; i++)
                #pragma unroll
                for (int j = 0; j < 4; j++)
                    acc[i][j] += a[i] * b[j];
        }
        __syncthreads();
    }

    #pragma unroll
    for (int i = 0; i < 4; i++) {
        int m = m0 + ty * 4 + i;
        #pragma unroll
        for (int j = 0; j < 4; j++) {
            int n = tx * 4 + j;
            Cp[(size_t)m * D_MODEL + n] = acc[i][j];
        }
    }
}

// ---------------------------------------------------------------------------
extern "C" void kernel_launch(void* const* d_in, const int* in_sizes, int n_in,
                              void* d_out, int out_size) {
    const float* x  = (const float*)d_in[0];
    const float* wq = (const float*)d_in[1];
    const float* bq = (const float*)d_in[2];
    const float* wk = (const float*)d_in[3];
    const float* bk = (const float*)d_in[4];
    const float* wv = (const float*)d_in[5];
    const float* bv = (const float*)d_in[6];
    const float* wo = (const float*)d_in[7];
    const float* bo = (const float*)d_in[8];

    float* out = (float*)d_out;

    float *qp, *kp, *vp, *cp, *attn_scratch;
    cudaGetSymbolAddress((void**)&qp, g_q);
    cudaGetSymbolAddress((void**)&kp, g_k);
    cudaGetSymbolAddress((void**)&vp, g_v);
    cudaGetSymbolAddress((void**)&cp, g_ctx);
    cudaGetSymbolAddress((void**)&attn_scratch, g_attn_scratch);

    // Decide where attn lives: inside d_out (tuple output) or scratch.
    float* attn;
    bool write_out = true;
    if ((size_t)out_size >= OUT_ELEMS + ATTN_ELEMS) {
        attn = out + OUT_ELEMS;               // (out, attn) concatenated
    } else if ((size_t)out_size == ATTN_ELEMS) {
        attn = out;                           // attn only (defensive)
        write_out = false;
    } else {
        attn = attn_scratch;                  // out only
    }

    dim3 blk(16, 16);

    // QKV projections
    gemm_nn_bias<<<dim3(D_MODEL / 64, ROWS / 64), blk>>>(x, wq, bq, qp, ROWS, D_MODEL, D_MODEL);
    gemm_nn_bias<<<dim3(D_MODEL / 64, ROWS / 64), blk>>>(x, wk, bk, kp, ROWS, D_MODEL, D_MODEL);
    gemm_nn_bias<<<dim3(D_MODEL / 64, ROWS / 64), blk>>>(x, wv, bv, vp, ROWS, D_MODEL, D_MODEL);

    // Attention
    logits_kernel<<<dim3(S_LEN / 64, S_LEN / 64, BH), blk>>>(qp, kp, attn);
    softmax_kernel<<<BH * S_LEN, 256>>>(attn);
    ctx_kernel<<<dim3(S_LEN / 64, 1, BH), blk>>>(attn, vp, cp);

    // Output projection
    if (write_out) {
        gemm_nn_bias<<<dim3(D_MODEL / 64, ROWS / 64), blk>>>(cp, wo, bo, out, ROWS, D_MODEL, D_MODEL);
    }
}

// round 3
// speedup vs baseline: 3.6071x; 3.6071x over previous
#include <cuda_runtime.h>
#include <math.h>
#include <stdint.h>

#define D_MODEL 1024
#define S_LEN   2048
#define BATCH   2
#define HEADS   16
#define DEPTH   64
#define ROWS    (BATCH * S_LEN)     // 4096
#define BH      (BATCH * HEADS)     // 32

#define OUT_ELEMS  ((size_t)ROWS * D_MODEL)              // 4,194,304
#define ATTN_ELEMS ((size_t)BH * S_LEN * S_LEN)          // 134,217,728

// Scratch (device globals — allocation-guard safe)
__device__ float g_q[ROWS * D_MODEL];
__device__ float g_k[ROWS * D_MODEL];
__device__ float g_v[ROWS * D_MODEL];
__device__ float g_ctx[ROWS * D_MODEL];
__device__ float g_attn_scratch[ATTN_ELEMS];

// ---------------------------------------------------------------------------
// tf32 helpers
// ---------------------------------------------------------------------------
__device__ __forceinline__ uint32_t f2tf32(float x) {
    uint32_t r;
    asm("cvt.rna.tf32.f32 %0, %1;" : "=r"(r) : "f"(x));
    return r;
}

// D += A*B ; m16n8k8 tf32, A row-major, B col-major, fp32 accum
__device__ __forceinline__ void mma8(float* c, const uint32_t* a, const uint32_t* b) {
    asm volatile(
        "mma.sync.aligned.m16n8k8.row.col.f32.tf32.tf32.f32 "
        "{%0,%1,%2,%3}, {%4,%5,%6,%7}, {%8,%9}, {%0,%1,%2,%3};"
        : "+f"(c[0]), "+f"(c[1]), "+f"(c[2]), "+f"(c[3])
        : "r"(a[0]), "r"(a[1]), "r"(a[2]), "r"(a[3]), "r"(b[0]), "r"(b[1]));
}

// ---------------------------------------------------------------------------
// NN GEMM + bias, tf32 tensor cores.
// C[M,N] = A[M,K] @ B[K,N] + bias.  BM=128, BN=128, BK=32.
// 256 threads = 8 warps (2 x 4); warp tile 64 x 32 (4 x 4 mma tiles).
// ---------------------------------------------------------------------------
__global__ void gemm_nn_tf32(const float* __restrict__ A,
                             const float* __restrict__ B,
                             const float* __restrict__ bias,
                             float* __restrict__ C,
                             int M, int N, int K) {
    __shared__ uint32_t As[128][36];   // pad 36: frag loads conflict-free
    __shared__ uint32_t Bs[32][136];   // pad 136: bank = 8k+n, conflict-free

    const int tid = threadIdx.x, lane = tid & 31, warp = tid >> 5;
    const int wm = warp >> 2, wn = warp & 3;
    const int g = lane >> 2, tg = lane & 3;
    const int m0 = blockIdx.y * 128, n0 = blockIdx.x * 128;

    float acc[4][4][4] = {};

    for (int kt = 0; kt < K; kt += 32) {
        #pragma unroll
        for (int i = 0; i < 4; i++) {
            int row = (tid >> 3) + i * 32;
            int col = (tid & 7) * 4;
            float4 v = *(const float4*)(A + (size_t)(m0 + row) * K + kt + col);
            As[row][col]     = f2tf32(v.x);
            As[row][col + 1] = f2tf32(v.y);
            As[row][col + 2] = f2tf32(v.z);
            As[row][col + 3] = f2tf32(v.w);
        }
        #pragma unroll
        for (int i = 0; i < 4; i++) {
            int k = (tid >> 5) + i * 8;
            int col = (tid & 31) * 4;
            float4 v = *(const float4*)(B + (size_t)(kt + k) * N + n0 + col);
            Bs[k][col]     = f2tf32(v.x);
            Bs[k][col + 1] = f2tf32(v.y);
            Bs[k][col + 2] = f2tf32(v.z);
            Bs[k][col + 3] = f2tf32(v.w);
        }
        __syncthreads();

        #pragma unroll
        for (int kk = 0; kk < 32; kk += 8) {
            uint32_t a[4][4], b[4][2];
            #pragma unroll
            for (int mi = 0; mi < 4; mi++) {
                int r = wm * 64 + mi * 16 + g;
                a[mi][0] = As[r][kk + tg];
                a[mi][1] = As[r + 8][kk + tg];
                a[mi][2] = As[r][kk + tg + 4];
                a[mi][3] = As[r + 8][kk + tg + 4];
            }
            #pragma unroll
            for (int ni = 0; ni < 4; ni++) {
                int c = wn * 32 + ni * 8 + g;
                b[ni][0] = Bs[kk + tg][c];
                b[ni][1] = Bs[kk + tg + 4][c];
            }
            #pragma unroll
            for (int mi = 0; mi < 4; mi++)
                #pragma unroll
                for (int ni = 0; ni < 4; ni++)
                    mma8(acc[mi][ni], a[mi], b[ni]);
        }
        __syncthreads();
    }

    #pragma unroll
    for (int mi = 0; mi < 4; mi++) {
        int r = m0 + wm * 64 + mi * 16 + g;
        #pragma unroll
        for (int ni = 0; ni < 4; ni++) {
            int c = n0 + wn * 32 + ni * 8 + 2 * tg;
            float b0 = bias ? bias[c] : 0.f;
            float b1 = bias ? bias[c + 1] : 0.f;
            *(float2*)(C + (size_t)r * N + c) =
                make_float2(acc[mi][ni][0] + b0, acc[mi][ni][1] + b1);
            *(float2*)(C + (size_t)(r + 8) * N + c) =
                make_float2(acc[mi][ni][2] + b0, acc[mi][ni][3] + b1);
        }
    }
}

// ---------------------------------------------------------------------------
// Logits: per (b,h): L[q][s] = 0.125 * sum_d Q[q][d]*K[s][d]   (NT gemm)
// BM=128 (q), BN=128 (s), full head dim K=64 in 2 x BK=32 steps.
// ---------------------------------------------------------------------------
__global__ void logits_tf32(const float* __restrict__ q,
                            const float* __restrict__ kmat,
                            float* __restrict__ attn) {
    __shared__ uint32_t Qs[128][36];
    __shared__ uint32_t Ks[128][36];

    const int bh = blockIdx.z;
    const int bb = bh >> 4, h = bh & 15;
    const float* Q  = q    + (size_t)bb * S_LEN * D_MODEL + h * DEPTH;
    const float* Kp = kmat + (size_t)bb * S_LEN * D_MODEL + h * DEPTH;
    float* out = attn + (size_t)bh * S_LEN * S_LEN;

    const int tid = threadIdx.x, lane = tid & 31, warp = tid >> 5;
    const int wm = warp >> 2, wn = warp & 3;
    const int g = lane >> 2, tg = lane & 3;
    const int m0 = blockIdx.y * 128, n0 = blockIdx.x * 128;

    float acc[4][4][4] = {};

    #pragma unroll
    for (int kt = 0; kt < DEPTH; kt += 32) {
        #pragma unroll
        for (int i = 0; i < 4; i++) {
            int row = (tid >> 3) + i * 32;
            int col = (tid & 7) * 4;
            float4 v = *(const float4*)(Q + (size_t)(m0 + row) * D_MODEL + kt + col);
            Qs[row][col]     = f2tf32(v.x);
            Qs[row][col + 1] = f2tf32(v.y);
            Qs[row][col + 2] = f2tf32(v.z);
            Qs[row][col + 3] = f2tf32(v.w);
        }
        #pragma unroll
        for (int i = 0; i < 4; i++) {
            int row = (tid >> 3) + i * 32;
            int col = (tid & 7) * 4;
            float4 v = *(const float4*)(Kp + (size_t)(n0 + row) * D_MODEL + kt + col);
            Ks[row][col]     = f2tf32(v.x);
            Ks[row][col + 1] = f2tf32(v.y);
            Ks[row][col + 2] = f2tf32(v.z);
            Ks[row][col + 3] = f2tf32(v.w);
        }
        __syncthreads();

        #pragma unroll
        for (int kk = 0; kk < 32; kk += 8) {
            uint32_t a[4][4], b[4][2];
            #pragma unroll
            for (int mi = 0; mi < 4; mi++) {
                int r = wm * 64 + mi * 16 + g;
                a[mi][0] = Qs[r][kk + tg];
                a[mi][1] = Qs[r + 8][kk + tg];
                a[mi][2] = Qs[r][kk + tg + 4];
                a[mi][3] = Qs[r + 8][kk + tg + 4];
            }
            #pragma unroll
            for (int ni = 0; ni < 4; ni++) {
                int c = wn * 32 + ni * 8 + g;
                b[ni][0] = Ks[c][kk + tg];
                b[ni][1] = Ks[c][kk + tg + 4];
            }
            #pragma unroll
            for (int mi = 0; mi < 4; mi++)
                #pragma unroll
                for (int ni = 0; ni < 4; ni++)
                    mma8(acc[mi][ni], a[mi], b[ni]);
        }
        __syncthreads();
    }

    const float scale = 0.125f;
    #pragma unroll
    for (int mi = 0; mi < 4; mi++) {
        int r = m0 + wm * 64 + mi * 16 + g;
        #pragma unroll
        for (int ni = 0; ni < 4; ni++) {
            int c = n0 + wn * 32 + ni * 8 + 2 * tg;
            *(float2*)(out + (size_t)r * S_LEN + c) =
                make_float2(acc[mi][ni][0] * scale, acc[mi][ni][1] * scale);
            *(float2*)(out + (size_t)(r + 8) * S_LEN + c) =
                make_float2(acc[mi][ni][2] * scale, acc[mi][ni][3] * scale);
        }
    }
}

// ---------------------------------------------------------------------------
// Softmax over rows of 2048. One block (256 thr) per row; all register-resident.
// ---------------------------------------------------------------------------
__global__ void softmax_kernel(float* __restrict__ attn) {
    __shared__ float red[8];

    float* p = attn + (size_t)blockIdx.x * S_LEN;
    const int tid = threadIdx.x;
    const int lane = tid & 31, warp = tid >> 5;

    float4 x0 = ((const float4*)p)[tid * 2];
    float4 x1 = ((const float4*)p)[tid * 2 + 1];

    float mx = fmaxf(fmaxf(fmaxf(x0.x, x0.y), fmaxf(x0.z, x0.w)),
                     fmaxf(fmaxf(x1.x, x1.y), fmaxf(x1.z, x1.w)));
    #pragma unroll
    for (int o = 16; o > 0; o >>= 1) mx = fmaxf(mx, __shfl_xor_sync(0xffffffffu, mx, o));
    if (lane == 0) red[warp] = mx;
    __syncthreads();
    if (warp == 0) {
        float v = (lane < 8) ? red[lane] : -INFINITY;
        #pragma unroll
        for (int o = 4; o > 0; o >>= 1) v = fmaxf(v, __shfl_xor_sync(0xffffffffu, v, o));
        if (lane == 0) red[0] = v;
    }
    __syncthreads();
    mx = red[0];

    x0.x = __expf(x0.x - mx); x0.y = __expf(x0.y - mx);
    x0.z = __expf(x0.z - mx); x0.w = __expf(x0.w - mx);
    x1.x = __expf(x1.x - mx); x1.y = __expf(x1.y - mx);
    x1.z = __expf(x1.z - mx); x1.w = __expf(x1.w - mx);

    float s = x0.x + x0.y + x0.z + x0.w + x1.x + x1.y + x1.z + x1.w;
    #pragma unroll
    for (int o = 16; o > 0; o >>= 1) s += __shfl_xor_sync(0xffffffffu, s, o);
    if (lane == 0) red[warp] = s;
    __syncthreads();
    if (warp == 0) {
        float v = (lane < 8) ? red[lane] : 0.f;
        #pragma unroll
        for (int o = 4; o > 0; o >>= 1) v += __shfl_xor_sync(0xffffffffu, v, o);
        if (lane == 0) red[0] = v;
    }
    __syncthreads();
    const float inv = 1.f / red[0];

    x0.x *= inv; x0.y *= inv; x0.z *= inv; x0.w *= inv;
    x1.x *= inv; x1.y *= inv; x1.z *= inv; x1.w *= inv;
    ((float4*)p)[tid * 2]     = x0;
    ((float4*)p)[tid * 2 + 1] = x1;
}

// ---------------------------------------------------------------------------
// Context: per (b,h): ctx[q][d] = sum_s attn[q][s] * V[s][d]  (NN, N=64)
// BM=128, BN=64, BK=32. 8 warps (4 x 2); warp tile 32 x 32 (2 x 4 mma tiles).
// ---------------------------------------------------------------------------
__global__ void ctx_tf32(const float* __restrict__ attn,
                         const float* __restrict__ v,
                         float* __restrict__ ctx) {
    __shared__ uint32_t As[128][36];
    __shared__ uint32_t Vs[32][72];   // pad 72: bank = 8k+n, conflict-free

    const int bh = blockIdx.z;
    const int bb = bh >> 4, h = bh & 15;
    const float* Ap = attn + (size_t)bh * S_LEN * S_LEN;
    const float* Vp = v + (size_t)bb * S_LEN * D_MODEL + h * DEPTH;
    float* Cp = ctx + (size_t)bb * S_LEN * D_MODEL + h * DEPTH;

    const int tid = threadIdx.x, lane = tid & 31, warp = tid >> 5;
    const int wm = warp >> 1, wn = warp & 1;
    const int g = lane >> 2, tg = lane & 3;
    const int m0 = blockIdx.x * 128;

    float acc[2][4][4] = {};

    for (int st = 0; st < S_LEN; st += 32) {
        #pragma unroll
        for (int i = 0; i < 4; i++) {
            int row = (tid >> 3) + i * 32;
            int col = (tid & 7) * 4;
            float4 w = *(const float4*)(Ap + (size_t)(m0 + row) * S_LEN + st + col);
            As[row][col]     = f2tf32(w.x);
            As[row][col + 1] = f2tf32(w.y);
            As[row][col + 2] = f2tf32(w.z);
            As[row][col + 3] = f2tf32(w.w);
        }
        #pragma unroll
        for (int i = 0; i < 2; i++) {
            int k = (tid >> 4) + i * 16;
            int col = (tid & 15) * 4;
            float4 w = *(const float4*)(Vp + (size_t)(st + k) * D_MODEL + col);
            Vs[k][col]     = f2tf32(w.x);
            Vs[k][col + 1] = f2tf32(w.y);
            Vs[k][col + 2] = f2tf32(w.z);
            Vs[k][col + 3] = f2tf32(w.w);
        }
        __syncthreads();

        #pragma unroll
        for (int kk = 0; kk < 32; kk += 8) {
            uint32_t a[2][4], b[4][2];
            #pragma unroll
            for (int mi = 0; mi < 2; mi++) {
                int r = wm * 32 + mi * 16 + g;
                a[mi][0] = As[r][kk + tg];
                a[mi][1] = As[r + 8][kk + tg];
                a[mi][2] = As[r][kk + tg + 4];
                a[mi][3] = As[r + 8][kk + tg + 4];
            }
            #pragma unroll
            for (int ni = 0; ni < 4; ni++) {
                int c = wn * 32 + ni * 8 + g;
                b[ni][0] = Vs[kk + tg][c];
                b[ni][1] = Vs[kk + tg + 4][c];
            }
            #pragma unroll
            for (int mi = 0; mi < 2; mi++)
                #pragma unroll
                for (int ni = 0; ni < 4; ni++)
                    mma8(acc[mi][ni], a[mi], b[ni]);
        }
        __syncthreads();
    }

    #pragma unroll
    for (int mi = 0; mi < 2; mi++) {
        int r = m0 + wm * 32 + mi * 16 + g;
        #pragma unroll
        for (int ni = 0; ni < 4; ni++) {
            int c = wn * 32 + ni * 8 + 2 * tg;
            *(float2*)(Cp + (size_t)r * D_MODEL + c) =
                make_float2(acc[mi][ni][0], acc[mi][ni][1]);
            *(float2*)(Cp + (size_t)(r + 8) * D_MODEL + c) =
                make_float2(acc[mi][ni][2], acc[mi][ni][3]);
        }
    }
}

// ---------------------------------------------------------------------------
extern "C" void kernel_launch(void* const* d_in, const int* in_sizes, int n_in,
                              void* d_out, int out_size) {
    const float* x  = (const float*)d_in[0];
    const float* wq = (const float*)d_in[1];
    const float* bq = (const float*)d_in[2];
    const float* wk = (const float*)d_in[3];
    const float* bk = (const float*)d_in[4];
    const float* wv = (const float*)d_in[5];
    const float* bv = (const float*)d_in[6];
    const float* wo = (const float*)d_in[7];
    const float* bo = (const float*)d_in[8];

    float* out = (float*)d_out;

    float *qp, *kp, *vp, *cp, *attn_scratch;
    cudaGetSymbolAddress((void**)&qp, g_q);
    cudaGetSymbolAddress((void**)&kp, g_k);
    cudaGetSymbolAddress((void**)&vp, g_v);
    cudaGetSymbolAddress((void**)&cp, g_ctx);
    cudaGetSymbolAddress((void**)&attn_scratch, g_attn_scratch);

    float* attn;
    bool write_out = true;
    if ((size_t)out_size >= OUT_ELEMS + ATTN_ELEMS) {
        attn = out + OUT_ELEMS;
    } else if ((size_t)out_size == ATTN_ELEMS) {
        attn = out;
        write_out = false;
    } else {
        attn = attn_scratch;
    }

    // QKV projections (tf32 tensor cores)
    gemm_nn_tf32<<<dim3(D_MODEL / 128, ROWS / 128), 256>>>(x, wq, bq, qp, ROWS, D_MODEL, D_MODEL);
    gemm_nn_tf32<<<dim3(D_MODEL / 128, ROWS / 128), 256>>>(x, wk, bk, kp, ROWS, D_MODEL, D_MODEL);
    gemm_nn_tf32<<<dim3(D_MODEL / 128, ROWS / 128), 256>>>(x, wv, bv, vp, ROWS, D_MODEL, D_MODEL);

    // Attention
    logits_tf32<<<dim3(S_LEN / 128, S_LEN / 128, BH), 256>>>(qp, kp, attn);
    softmax_kernel<<<BH * S_LEN, 256>>>(attn);
    ctx_tf32<<<dim3(S_LEN / 128, 1, BH), 256>>>(attn, vp, cp);

    // Output projection
    if (write_out) {
        gemm_nn_tf32<<<dim3(D_MODEL / 128, ROWS / 128), 256>>>(cp, wo, bo, out, ROWS, D_MODEL, D_MODEL);
    }
}

// round 4
// speedup vs baseline: 4.5772x; 1.2689x over previous
#include <cuda_runtime.h>
#include <math.h>
#include <stdint.h>

#define D_MODEL 1024
#define S_LEN   2048
#define BATCH   2
#define HEADS   16
#define DEPTH   64
#define ROWS    (BATCH * S_LEN)     // 4096
#define BH      (BATCH * HEADS)     // 32

#define OUT_ELEMS  ((size_t)ROWS * D_MODEL)
#define ATTN_ELEMS ((size_t)BH * S_LEN * S_LEN)

__device__ float g_q[ROWS * D_MODEL];
__device__ float g_k[ROWS * D_MODEL];
__device__ float g_v[ROWS * D_MODEL];
__device__ float g_ctx[ROWS * D_MODEL];
__device__ float g_attn_scratch[ATTN_ELEMS];

// ---------------------------------------------------------------------------
#define CPA(dst, src) asm volatile("cp.async.cg.shared.global [%0], [%1], 16;" :: "r"(dst), "l"(src))
#define CPC()         asm volatile("cp.async.commit_group;")
#define CPW(n)        asm volatile("cp.async.wait_group %0;" :: "n"(n))

__device__ __forceinline__ uint32_t f2tf32(float x) {
    uint32_t r;
    asm("cvt.rna.tf32.f32 %0, %1;" : "=r"(r) : "f"(x));
    return r;
}

__device__ __forceinline__ void mma8(float* c, const uint32_t* a, const uint32_t* b) {
    asm volatile(
        "mma.sync.aligned.m16n8k8.row.col.f32.tf32.tf32.f32 "
        "{%0,%1,%2,%3}, {%4,%5,%6,%7}, {%8,%9}, {%0,%1,%2,%3};"
        : "+f"(c[0]), "+f"(c[1]), "+f"(c[2]), "+f"(c[3])
        : "r"(a[0]), "r"(a[1]), "r"(a[2]), "r"(a[3]), "r"(b[0]), "r"(b[1]));
}

__device__ __forceinline__ uint32_t sptr(const void* p) {
    return (uint32_t)__cvta_generic_to_shared(p);
}

// ---------------------------------------------------------------------------
// NN GEMM + bias, up to 3 weight segments (QKV fused). BM=128 BN=128 BK=32.
// Double-buffered cp.async. 8 warps (2x4), warp tile 64x32.
// Dynamic smem: As 2*128*36 floats, Bs 2*32*136 floats = 71680 B.
// ---------------------------------------------------------------------------
__global__ void __launch_bounds__(256, 2) gemm_x3(
    const float* __restrict__ A,
    const float* __restrict__ B0, const float* __restrict__ B1, const float* __restrict__ B2,
    const float* __restrict__ bi0, const float* __restrict__ bi1, const float* __restrict__ bi2,
    float* __restrict__ C0, float* __restrict__ C1, float* __restrict__ C2) {
    extern __shared__ float sm[];
    float* AsB = sm;            // 2 * 4608
    float* BsB = sm + 9216;     // 2 * 4352

    const int K = D_MODEL, N = D_MODEL;
    const int sel = blockIdx.x >> 3;
    const float* B    = sel == 0 ? B0  : (sel == 1 ? B1  : B2);
    const float* bias = sel == 0 ? bi0 : (sel == 1 ? bi1 : bi2);
    float* C          = sel == 0 ? C0  : (sel == 1 ? C1  : C2);
    const int n0 = (blockIdx.x & 7) * 128;
    const int m0 = blockIdx.y * 128;

    const int tid = threadIdx.x, lane = tid & 31, warp = tid >> 5;
    const int wm = warp >> 2, wn = warp & 3;
    const int g = lane >> 2, tg = lane & 3;
    const int arow = tid >> 3, acol = (tid & 7) * 4;
    const int bk = tid >> 5, bcol = (tid & 31) * 4;

    float acc[4][4][4] = {};

#define PREFETCH_G(kt, buf) {                                                    \
        float* As_ = AsB + (buf) * 4608;                                         \
        float* Bs_ = BsB + (buf) * 4352;                                         \
        _Pragma("unroll")                                                        \
        for (int i = 0; i < 4; i++)                                              \
            CPA(sptr(&As_[(arow + i * 32) * 36 + acol]),                         \
                A + (size_t)(m0 + arow + i * 32) * K + (kt) + acol);             \
        _Pragma("unroll")                                                        \
        for (int i = 0; i < 4; i++)                                              \
            CPA(sptr(&Bs_[(bk + i * 8) * 136 + bcol]),                           \
                B + (size_t)((kt) + bk + i * 8) * N + n0 + bcol);                \
    }

    PREFETCH_G(0, 0); CPC();

    const int NT = K / 32;
    for (int t = 0; t < NT; t++) {
        CPW(0);
        __syncthreads();
        if (t + 1 < NT) { PREFETCH_G((t + 1) * 32, (t + 1) & 1); CPC(); }

        const float* As = AsB + (t & 1) * 4608;
        const float* Bs = BsB + (t & 1) * 4352;
        #pragma unroll
        for (int kk = 0; kk < 32; kk += 8) {
            uint32_t a[4][4], b[4][2];
            #pragma unroll
            for (int mi = 0; mi < 4; mi++) {
                int r = wm * 64 + mi * 16 + g;
                a[mi][0] = f2tf32(As[r * 36 + kk + tg]);
                a[mi][1] = f2tf32(As[(r + 8) * 36 + kk + tg]);
                a[mi][2] = f2tf32(As[r * 36 + kk + tg + 4]);
                a[mi][3] = f2tf32(As[(r + 8) * 36 + kk + tg + 4]);
            }
            #pragma unroll
            for (int ni = 0; ni < 4; ni++) {
                int c = wn * 32 + ni * 8 + g;
                b[ni][0] = f2tf32(Bs[(kk + tg) * 136 + c]);
                b[ni][1] = f2tf32(Bs[(kk + tg + 4) * 136 + c]);
            }
            #pragma unroll
            for (int mi = 0; mi < 4; mi++)
                #pragma unroll
                for (int ni = 0; ni < 4; ni++)
                    mma8(acc[mi][ni], a[mi], b[ni]);
        }
        __syncthreads();
    }
#undef PREFETCH_G

    #pragma unroll
    for (int mi = 0; mi < 4; mi++) {
        int r = m0 + wm * 64 + mi * 16 + g;
        #pragma unroll
        for (int ni = 0; ni < 4; ni++) {
            int c = n0 + wn * 32 + ni * 8 + 2 * tg;
            float b0 = bias[c], b1 = bias[c + 1];
            *(float2*)(C + (size_t)r * N + c) =
                make_float2(acc[mi][ni][0] + b0, acc[mi][ni][1] + b1);
            *(float2*)(C + (size_t)(r + 8) * N + c) =
                make_float2(acc[mi][ni][2] + b0, acc[mi][ni][3] + b1);
        }
    }
}

// ---------------------------------------------------------------------------
// Logits NT GEMM: L[q][s] = 0.125 * sum_d Q[q][d]*K[s][d].  BM=BN=128, BK=32x2.
// Both depth tiles prefetched upfront (DEPTH=64). Smem 73728 B.
// ---------------------------------------------------------------------------
__global__ void __launch_bounds__(256, 2) logits_tf32(
    const float* __restrict__ q, const float* __restrict__ kmat,
    float* __restrict__ attn) {
    extern __shared__ float sm[];
    float* QsB = sm;            // 2 * 4608
    float* KsB = sm + 9216;     // 2 * 4608

    const int bh = blockIdx.z;
    const int bb = bh >> 4, h = bh & 15;
    const float* Q  = q    + (size_t)bb * S_LEN * D_MODEL + h * DEPTH;
    const float* Kp = kmat + (size_t)bb * S_LEN * D_MODEL + h * DEPTH;
    float* out = attn + (size_t)bh * S_LEN * S_LEN;

    const int tid = threadIdx.x, lane = tid & 31, warp = tid >> 5;
    const int wm = warp >> 2, wn = warp & 3;
    const int g = lane >> 2, tg = lane & 3;
    const int m0 = blockIdx.y * 128, n0 = blockIdx.x * 128;
    const int arow = tid >> 3, acol = (tid & 7) * 4;

    float acc[4][4][4] = {};

#define PREFETCH_QK(kt, buf) {                                                   \
        float* Qs_ = QsB + (buf) * 4608;                                         \
        float* Ks_ = KsB + (buf) * 4608;                                         \
        _Pragma("unroll")                                                        \
        for (int i = 0; i < 4; i++)                                              \
            CPA(sptr(&Qs_[(arow + i * 32) * 36 + acol]),                         \
                Q + (size_t)(m0 + arow + i * 32) * D_MODEL + (kt) + acol);       \
        _Pragma("unroll")                                                        \
        for (int i = 0; i < 4; i++)                                              \
            CPA(sptr(&Ks_[(arow + i * 32) * 36 + acol]),                         \
                Kp + (size_t)(n0 + arow + i * 32) * D_MODEL + (kt) + acol);      \
    }

    PREFETCH_QK(0, 0); CPC();
    PREFETCH_QK(32, 1); CPC();

    #pragma unroll
    for (int t = 0; t < 2; t++) {
        if (t == 0) CPW(1); else CPW(0);
        __syncthreads();
        const float* Qs = QsB + t * 4608;
        const float* Ks = KsB + t * 4608;
        #pragma unroll
        for (int kk = 0; kk < 32; kk += 8) {
            uint32_t a[4][4], b[4][2];
            #pragma unroll
            for (int mi = 0; mi < 4; mi++) {
                int r = wm * 64 + mi * 16 + g;
                a[mi][0] = f2tf32(Qs[r * 36 + kk + tg]);
                a[mi][1] = f2tf32(Qs[(r + 8) * 36 + kk + tg]);
                a[mi][2] = f2tf32(Qs[r * 36 + kk + tg + 4]);
                a[mi][3] = f2tf32(Qs[(r + 8) * 36 + kk + tg + 4]);
            }
            #pragma unroll
            for (int ni = 0; ni < 4; ni++) {
                int c = wn * 32 + ni * 8 + g;
                b[ni][0] = f2tf32(Ks[c * 36 + kk + tg]);
                b[ni][1] = f2tf32(Ks[c * 36 + kk + tg + 4]);
            }
            #pragma unroll
            for (int mi = 0; mi < 4; mi++)
                #pragma unroll
                for (int ni = 0; ni < 4; ni++)
                    mma8(acc[mi][ni], a[mi], b[ni]);
        }
        __syncthreads();
    }
#undef PREFETCH_QK

    const float scale = 0.125f;
    #pragma unroll
    for (int mi = 0; mi < 4; mi++) {
        int r = m0 + wm * 64 + mi * 16 + g;
        #pragma unroll
        for (int ni = 0; ni < 4; ni++) {
            int c = n0 + wn * 32 + ni * 8 + 2 * tg;
            *(float2*)(out + (size_t)r * S_LEN + c) =
                make_float2(acc[mi][ni][0] * scale, acc[mi][ni][1] * scale);
            *(float2*)(out + (size_t)(r + 8) * S_LEN + c) =
                make_float2(acc[mi][ni][2] * scale, acc[mi][ni][3] * scale);
        }
    }
}

// ---------------------------------------------------------------------------
// Softmax over rows of 2048. One block (256 thr) per row, register-resident.
// ---------------------------------------------------------------------------
__global__ void softmax_kernel(float* __restrict__ attn) {
    __shared__ float red[8];

    float* p = attn + (size_t)blockIdx.x * S_LEN;
    const int tid = threadIdx.x;
    const int lane = tid & 31, warp = tid >> 5;

    float4 x0 = ((const float4*)p)[tid * 2];
    float4 x1 = ((const float4*)p)[tid * 2 + 1];

    float mx = fmaxf(fmaxf(fmaxf(x0.x, x0.y), fmaxf(x0.z, x0.w)),
                     fmaxf(fmaxf(x1.x, x1.y), fmaxf(x1.z, x1.w)));
    #pragma unroll
    for (int o = 16; o > 0; o >>= 1) mx = fmaxf(mx, __shfl_xor_sync(0xffffffffu, mx, o));
    if (lane == 0) red[warp] = mx;
    __syncthreads();
    if (warp == 0) {
        float v = (lane < 8) ? red[lane] : -INFINITY;
        #pragma unroll
        for (int o = 4; o > 0; o >>= 1) v = fmaxf(v, __shfl_xor_sync(0xffffffffu, v, o));
        if (lane == 0) red[0] = v;
    }
    __syncthreads();
    mx = red[0];

    x0.x = __expf(x0.x - mx); x0.y = __expf(x0.y - mx);
    x0.z = __expf(x0.z - mx); x0.w = __expf(x0.w - mx);
    x1.x = __expf(x1.x - mx); x1.y = __expf(x1.y - mx);
    x1.z = __expf(x1.z - mx); x1.w = __expf(x1.w - mx);

    float s = x0.x + x0.y + x0.z + x0.w + x1.x + x1.y + x1.z + x1.w;
    #pragma unroll
    for (int o = 16; o > 0; o >>= 1) s += __shfl_xor_sync(0xffffffffu, s, o);
    if (lane == 0) red[warp] = s;
    __syncthreads();
    if (warp == 0) {
        float v = (lane < 8) ? red[lane] : 0.f;
        #pragma unroll
        for (int o = 4; o > 0; o >>= 1) v += __shfl_xor_sync(0xffffffffu, v, o);
        if (lane == 0) red[0] = v;
    }
    __syncthreads();
    const float inv = 1.f / red[0];

    x0.x *= inv; x0.y *= inv; x0.z *= inv; x0.w *= inv;
    x1.x *= inv; x1.y *= inv; x1.z *= inv; x1.w *= inv;
    ((float4*)p)[tid * 2]     = x0;
    ((float4*)p)[tid * 2 + 1] = x1;
}

// ---------------------------------------------------------------------------
// Context NN GEMM: ctx[q][d] = sum_s attn[q][s]*V[s][d].  BM=128 BN=64 BK=32.
// Double-buffered cp.async over 64 s-tiles. Smem 55296 B.
// 8 warps (4x2), warp tile 32x32.
// ---------------------------------------------------------------------------
__global__ void __launch_bounds__(256, 2) ctx_tf32(
    const float* __restrict__ attn, const float* __restrict__ v,
    float* __restrict__ ctx) {
    extern __shared__ float sm[];
    float* AsB = sm;            // 2 * 4608
    float* VsB = sm + 9216;     // 2 * 2304

    const int bh = blockIdx.z;
    const int bb = bh >> 4, h = bh & 15;
    const float* Ap = attn + (size_t)bh * S_LEN * S_LEN;
    const float* Vp = v + (size_t)bb * S_LEN * D_MODEL + h * DEPTH;
    float* Cp = ctx + (size_t)bb * S_LEN * D_MODEL + h * DEPTH;

    const int tid = threadIdx.x, lane = tid & 31, warp = tid >> 5;
    const int wm = warp >> 1, wn = warp & 1;
    const int g = lane >> 2, tg = lane & 3;
    const int m0 = blockIdx.x * 128;
    const int arow = tid >> 3, acol = (tid & 7) * 4;
    const int vk = tid >> 4, vcol = (tid & 15) * 4;

    float acc[2][4][4] = {};

#define PREFETCH_AV(st, buf) {                                                   \
        float* As_ = AsB + (buf) * 4608;                                         \
        float* Vs_ = VsB + (buf) * 2304;                                         \
        _Pragma("unroll")                                                        \
        for (int i = 0; i < 4; i++)                                              \
            CPA(sptr(&As_[(arow + i * 32) * 36 + acol]),                         \
                Ap + (size_t)(m0 + arow + i * 32) * S_LEN + (st) + acol);        \
        _Pragma("unroll")                                                        \
        for (int i = 0; i < 2; i++)                                              \
            CPA(sptr(&Vs_[(vk + i * 16) * 72 + vcol]),                           \
                Vp + (size_t)((st) + vk + i * 16) * D_MODEL + vcol);             \
    }

    PREFETCH_AV(0, 0); CPC();

    const int NT = S_LEN / 32;
    for (int t = 0; t < NT; t++) {
        CPW(0);
        __syncthreads();
        if (t + 1 < NT) { PREFETCH_AV((t + 1) * 32, (t + 1) & 1); CPC(); }

        const float* As = AsB + (t & 1) * 4608;
        const float* Vs = VsB + (t & 1) * 2304;
        #pragma unroll
        for (int kk = 0; kk < 32; kk += 8) {
            uint32_t a[2][4], b[4][2];
            #pragma unroll
            for (int mi = 0; mi < 2; mi++) {
                int r = wm * 32 + mi * 16 + g;
                a[mi][0] = f2tf32(As[r * 36 + kk + tg]);
                a[mi][1] = f2tf32(As[(r + 8) * 36 + kk + tg]);
                a[mi][2] = f2tf32(As[r * 36 + kk + tg + 4]);
                a[mi][3] = f2tf32(As[(r + 8) * 36 + kk + tg + 4]);
            }
            #pragma unroll
            for (int ni = 0; ni < 4; ni++) {
                int c = wn * 32 + ni * 8 + g;
                b[ni][0] = f2tf32(Vs[(kk + tg) * 72 + c]);
                b[ni][1] = f2tf32(Vs[(kk + tg + 4) * 72 + c]);
            }
            #pragma unroll
            for (int mi = 0; mi < 2; mi++)
                #pragma unroll
                for (int ni = 0; ni < 4; ni++)
                    mma8(acc[mi][ni], a[mi], b[ni]);
        }
        __syncthreads();
    }
#undef PREFETCH_AV

    #pragma unroll
    for (int mi = 0; mi < 2; mi++) {
        int r = m0 + wm * 32 + mi * 16 + g;
        #pragma unroll
        for (int ni = 0; ni < 4; ni++) {
            int c = wn * 32 + ni * 8 + 2 * tg;
            *(float2*)(Cp + (size_t)r * D_MODEL + c) =
                make_float2(acc[mi][ni][0], acc[mi][ni][1]);
            *(float2*)(Cp + (size_t)(r + 8) * D_MODEL + c) =
                make_float2(acc[mi][ni][2], acc[mi][ni][3]);
        }
    }
}

// ---------------------------------------------------------------------------
extern "C" void kernel_launch(void* const* d_in, const int* in_sizes, int n_in,
                              void* d_out, int out_size) {
    const float* x  = (const float*)d_in[0];
    const float* wq = (const float*)d_in[1];
    const float* bq = (const float*)d_in[2];
    const float* wk = (const float*)d_in[3];
    const float* bk = (const float*)d_in[4];
    const float* wv = (const float*)d_in[5];
    const float* bv = (const float*)d_in[6];
    const float* wo = (const float*)d_in[7];
    const float* bo = (const float*)d_in[8];

    float* out = (float*)d_out;

    float *qp, *kp, *vp, *cp, *attn_scratch;
    cudaGetSymbolAddress((void**)&qp, g_q);
    cudaGetSymbolAddress((void**)&kp, g_k);
    cudaGetSymbolAddress((void**)&vp, g_v);
    cudaGetSymbolAddress((void**)&cp, g_ctx);
    cudaGetSymbolAddress((void**)&attn_scratch, g_attn_scratch);

    float* attn;
    bool write_out = true;
    if ((size_t)out_size >= OUT_ELEMS + ATTN_ELEMS) {
        attn = out + OUT_ELEMS;
    } else if ((size_t)out_size == ATTN_ELEMS) {
        attn = out;
        write_out = false;
    } else {
        attn = attn_scratch;
    }

    const int GEMM_SMEM   = (9216 + 8704) * 4;   // 71680
    const int LOGITS_SMEM = (9216 + 9216) * 4;   // 73728
    const int CTX_SMEM    = (9216 + 4608) * 4;   // 55296
    cudaFuncSetAttribute(gemm_x3,     cudaFuncAttributeMaxDynamicSharedMemorySize, GEMM_SMEM);
    cudaFuncSetAttribute(logits_tf32, cudaFuncAttributeMaxDynamicSharedMemorySize, LOGITS_SMEM);
    cudaFuncSetAttribute(ctx_tf32,    cudaFuncAttributeMaxDynamicSharedMemorySize, CTX_SMEM);

    // Fused QKV projections
    gemm_x3<<<dim3(24, ROWS / 128), 256, GEMM_SMEM>>>(
        x, wq, wk, wv, bq, bk, bv, qp, kp, vp);

    // Attention
    logits_tf32<<<dim3(S_LEN / 128, S_LEN / 128, BH), 256, LOGITS_SMEM>>>(qp, kp, attn);
    softmax_kernel<<<BH * S_LEN, 256>>>(attn);
    ctx_tf32<<<dim3(S_LEN / 128, 1, BH), 256, CTX_SMEM>>>(attn, vp, cp);

    // Output projection
    if (write_out) {
        gemm_x3<<<dim3(8, ROWS / 128), 256, GEMM_SMEM>>>(
            cp, wo, wo, wo, bo, bo, bo, out, out, out);
    }
}